// round 13
// baseline (speedup 1.0000x reference)
#include <cuda_runtime.h>
#include <cuda_bf16.h>
#include <cstdint>
#include <cstddef>

#define N_LOCS 81
#define BATCH  2048
#define EMB    256
#define ELEMS  (BATCH * N_LOCS * EMB)
#define WS_ELEMS (7 * N_LOCS * EMB * EMB)
#define W0_ELEMS (N_LOCS * EMB * 64)

__device__ float  g_bufZ[ELEMS];
__device__ __nv_bfloat16 g_yh[ELEMS];
__device__ __nv_bfloat16 g_yl[ELEMS];
__device__ __nv_bfloat16 g_ah0[ELEMS];
__device__ __nv_bfloat16 g_al0[ELEMS];
__device__ __nv_bfloat16 g_ah1[ELEMS];
__device__ __nv_bfloat16 g_al1[ELEMS];
__device__ __nv_bfloat16 g_wth[WS_ELEMS];
__device__ __nv_bfloat16 g_wtl[WS_ELEMS];
__device__ __nv_bfloat16 g_w0h[W0_ELEMS];
__device__ __nv_bfloat16 g_w0l[W0_ELEMS];
__device__ __nv_bfloat16 g_Ah96[96 * 96];
__device__ __nv_bfloat16 g_Al96[96 * 96];
__device__ double g_sum[N_LOCS];
__device__ double g_sumsq[N_LOCS];
__device__ float  g_scale[N_LOCS];
__device__ float  g_shift[N_LOCS];

__device__ __forceinline__ uint32_t s2u(const void* p) {
    uint32_t a;
    asm("{ .reg .u64 t; cvta.to.shared.u64 t, %1; cvt.u32.u64 %0, t; }" : "=r"(a) : "l"(p));
    return a;
}
__device__ __forceinline__ void cp16(uint32_t s, const void* g) {
    asm volatile("cp.async.cg.shared.global [%0], [%1], 16;" :: "r"(s), "l"(g) : "memory");
}
__device__ __forceinline__ void cp_commit() {
    asm volatile("cp.async.commit_group;" ::: "memory");
}
template <int N>
__device__ __forceinline__ void cp_wait() {
    asm volatile("cp.async.wait_group %0;" :: "n"(N) : "memory");
}
#define LDSM_X4(r0, r1, r2, r3, addr) \
    asm volatile("ldmatrix.sync.aligned.m8n8.x4.shared.b16 {%0,%1,%2,%3}, [%4];" \
                 : "=r"(r0), "=r"(r1), "=r"(r2), "=r"(r3) : "r"(addr))
#define LDSM_X2(r0, r1, addr) \
    asm volatile("ldmatrix.sync.aligned.m8n8.x2.shared.b16 {%0,%1}, [%2];" \
                 : "=r"(r0), "=r"(r1) : "r"(addr))
#define LDSM_X2T(r0, r1, addr) \
    asm volatile("ldmatrix.sync.aligned.m8n8.x2.trans.shared.b16 {%0,%1}, [%2];" \
                 : "=r"(r0), "=r"(r1) : "r"(addr))
#define MMA_BF16(d, a, b) \
    asm volatile("mma.sync.aligned.m16n8k16.row.col.f32.bf16.bf16.f32 " \
                 "{%0,%1,%2,%3}, {%4,%5,%6,%7}, {%8,%9}, {%0,%1,%2,%3};" \
                 : "+f"((d)[0]), "+f"((d)[1]), "+f"((d)[2]), "+f"((d)[3]) \
                 : "r"((a)[0]), "r"((a)[1]), "r"((a)[2]), "r"((a)[3]), \
                   "r"((b)[0]), "r"((b)[1]))

__device__ __forceinline__ uint32_t pack2bf(float a, float b) {
    __nv_bfloat162 t;
    t.x = __float2bfloat16(a); t.y = __float2bfloat16(b);
    return *reinterpret_cast<uint32_t*>(&t);
}

#define ROWB   80
#define TILE_B 10240
#define STAGE_B 40960
#define GEMM_SMEM (2 * STAGE_B)

// ============ stage 1a: block-0 GEMM (128x128 tile, R7-proven) ===============
__global__ __launch_bounds__(256, 2)
void gemm0_kernel(const float* __restrict__ X,
                  const __nv_bfloat16* __restrict__ Wh, const __nv_bfloat16* __restrict__ Wl,
                  __nv_bfloat16* __restrict__ Yh, __nv_bfloat16* __restrict__ Yl,
                  int K, int Kpad)
{
    extern __shared__ char smem[];
    const uint32_t sb = s2u(smem);
    const int tid = threadIdx.x, wid = tid >> 5, lane = tid & 31;
    const int wm = wid >> 2, wn = wid & 3;
    const int n = blockIdx.z, mBase = blockIdx.x * 128, nBase = blockIdx.y * 128;
    const int ldx = N_LOCS * K;
    const float* Xn = X + (size_t)n * K;
    const __nv_bfloat16* Whn = Wh + (size_t)n * EMB * Kpad;
    const __nv_bfloat16* Wln = Wl + (size_t)n * EMB * Kpad;

    float acc[4][4][4];
#pragma unroll
    for (int mt = 0; mt < 4; mt++)
#pragma unroll
        for (int nt = 0; nt < 4; nt++)
#pragma unroll
            for (int q = 0; q < 4; q++) acc[mt][nt][q] = 0.f;

    const int nchunk = Kpad >> 5;

    auto load_chunk = [&](int c) {
        const uint32_t stOff = (c & 1) * STAGE_B;
        const int k0 = c << 5;
        for (int it = 0; it < 16; it++) {
            int idx = tid + (it << 8);
            int r = idx >> 5, kk = idx & 31;
            int k = k0 + kk;
            float v = (k < K) ? Xn[(size_t)(mBase + r) * ldx + k] : 0.f;
            float h = __bfloat162float(__float2bfloat16(v));
            uint32_t so = stOff + r * ROWB + kk * 2;
            *reinterpret_cast<__nv_bfloat16*>(smem + so)          = __float2bfloat16(v);
            *reinterpret_cast<__nv_bfloat16*>(smem + so + TILE_B) = __float2bfloat16(v - h);
        }
#pragma unroll
        for (int it = 0; it < 2; it++) {
            int idx = tid + (it << 8);
            int r = idx >> 2, j = idx & 3;
            size_t go = (size_t)(nBase + r) * Kpad + k0 + j * 8;
            uint32_t so = sb + stOff + 2 * TILE_B + r * ROWB + j * 16;
            cp16(so,          Whn + go);
            cp16(so + TILE_B, Wln + go);
        }
        cp_commit();
    };

    load_chunk(0);
    for (int c = 0; c < nchunk; c++) {
        if (c + 1 < nchunk) { load_chunk(c + 1); cp_wait<1>(); }
        else                { cp_wait<0>(); }
        __syncthreads();
        const uint32_t st  = sb + (c & 1) * STAGE_B;
        const uint32_t sAh = st, sAl = st + TILE_B;
        const uint32_t sBh = st + 2 * TILE_B, sBl = st + 3 * TILE_B;
#pragma unroll
        for (int ks = 0; ks < 2; ks++) {
            uint32_t bh[4][2], bl[4][2];
            const uint32_t bOff = (wn * 32 + (lane & 7)) * ROWB
                                  + ks * 32 + ((lane >> 3) & 1) * 16;
#pragma unroll
            for (int nt = 0; nt < 4; nt++) {
                LDSM_X2(bh[nt][0], bh[nt][1], sBh + bOff + nt * 8 * ROWB);
                LDSM_X2(bl[nt][0], bl[nt][1], sBl + bOff + nt * 8 * ROWB);
            }
            const uint32_t aOff = (wm * 64 + (lane & 15)) * ROWB
                                  + ks * 32 + (lane >> 4) * 16;
#pragma unroll
            for (int mt = 0; mt < 4; mt++) {
                uint32_t ah[4], al[4];
                LDSM_X4(ah[0], ah[1], ah[2], ah[3], sAh + aOff + mt * 16 * ROWB);
                LDSM_X4(al[0], al[1], al[2], al[3], sAl + aOff + mt * 16 * ROWB);
#pragma unroll
                for (int nt = 0; nt < 4; nt++) {
                    MMA_BF16(acc[mt][nt], ah, bh[nt]);
                    MMA_BF16(acc[mt][nt], ah, bl[nt]);
                    MMA_BF16(acc[mt][nt], al, bh[nt]);
                }
            }
        }
        __syncthreads();
    }
#pragma unroll
    for (int mt = 0; mt < 4; mt++) {
        int row0 = mBase + wm * 64 + mt * 16 + (lane >> 2);
#pragma unroll
        for (int nt = 0; nt < 4; nt++) {
            int col = nBase + wn * 32 + nt * 8 + 2 * (lane & 3);
            size_t o0 = ((size_t)row0 * N_LOCS + n) * EMB + col;
            size_t o1 = ((size_t)(row0 + 8) * N_LOCS + n) * EMB + col;
            float f0 = acc[mt][nt][0], f1 = acc[mt][nt][1];
            float f2 = acc[mt][nt][2], f3 = acc[mt][nt][3];
            float h0 = __bfloat162float(__float2bfloat16(f0));
            float h1 = __bfloat162float(__float2bfloat16(f1));
            float h2 = __bfloat162float(__float2bfloat16(f2));
            float h3 = __bfloat162float(__float2bfloat16(f3));
            *reinterpret_cast<uint32_t*>(Yh + o0) = pack2bf(f0, f1);
            *reinterpret_cast<uint32_t*>(Yl + o0) = pack2bf(f0 - h0, f1 - h1);
            *reinterpret_cast<uint32_t*>(Yh + o1) = pack2bf(f2, f3);
            *reinterpret_cast<uint32_t*>(Yl + o1) = pack2bf(f2 - h2, f3 - h3);
        }
    }
}

// ==== stage 1b: GEMM 256x128 CTA tile, 64x64 warp tile (smem-traffic cut) ====
#define G2_AT   20480                 // A half tile: 256*80
#define G2_BT   10240                 // B half tile: 128*80
#define G2_STG  61440                 // stage: 2*A + 2*B
#define GEMM2_SMEM (2 * G2_STG)       // 122880

__global__ __launch_bounds__(256, 1)
void gemm_mma_kernel(const __nv_bfloat16* __restrict__ Xh, const __nv_bfloat16* __restrict__ Xl,
                     const __nv_bfloat16* __restrict__ Wh, const __nv_bfloat16* __restrict__ Wl,
                     __nv_bfloat16* __restrict__ Yh, __nv_bfloat16* __restrict__ Yl)
{
    extern __shared__ char smem[];
    const uint32_t sb = s2u(smem);
    const int tid = threadIdx.x, wid = tid >> 5, lane = tid & 31;
    const int wm = wid >> 1, wn = wid & 1;         // 4 m-groups x 2 n-groups
    const int n = blockIdx.z, mBase = blockIdx.x * 256, nBase = blockIdx.y * 128;
    const int ldx = N_LOCS * EMB;
    const __nv_bfloat16* Xhn = Xh + (size_t)n * EMB;
    const __nv_bfloat16* Xln = Xl + (size_t)n * EMB;
    const __nv_bfloat16* Whn = Wh + (size_t)n * EMB * EMB;
    const __nv_bfloat16* Wln = Wl + (size_t)n * EMB * EMB;

    float acc[4][8][4];
#pragma unroll
    for (int mt = 0; mt < 4; mt++)
#pragma unroll
        for (int nt = 0; nt < 8; nt++)
#pragma unroll
            for (int q = 0; q < 4; q++) acc[mt][nt][q] = 0.f;

    auto load_chunk = [&](int c) {
        const uint32_t st = sb + (c & 1) * G2_STG;
        const int k0 = c << 5;
#pragma unroll
        for (int it = 0; it < 4; it++) {           // A: 256 rows x 4 segs
            int idx = tid + (it << 8);
            int r = idx >> 2, j = idx & 3;
            size_t go = (size_t)(mBase + r) * ldx + k0 + j * 8;
            uint32_t so = st + r * ROWB + j * 16;
            cp16(so,         Xhn + go);
            cp16(so + G2_AT, Xln + go);
        }
#pragma unroll
        for (int it = 0; it < 2; it++) {           // B: 128 rows x 4 segs
            int idx = tid + (it << 8);
            int r = idx >> 2, j = idx & 3;
            size_t go = (size_t)(nBase + r) * EMB + k0 + j * 8;
            uint32_t so = st + 2 * G2_AT + r * ROWB + j * 16;
            cp16(so,         Whn + go);
            cp16(so + G2_BT, Wln + go);
        }
        cp_commit();
    };

    load_chunk(0);
#pragma unroll 1
    for (int c = 0; c < 8; c++) {
        if (c + 1 < 8) { load_chunk(c + 1); cp_wait<1>(); }
        else           { cp_wait<0>(); }
        __syncthreads();
        const uint32_t st  = sb + (c & 1) * G2_STG;
        const uint32_t sAh = st, sAl = st + G2_AT;
        const uint32_t sBh = st + 2 * G2_AT, sBl = sBh + G2_BT;
#pragma unroll
        for (int ks = 0; ks < 2; ks++) {
            uint32_t bh[8][2], bl[8][2];
            const uint32_t bOff = (wn * 64 + (lane & 7)) * ROWB
                                  + ks * 32 + ((lane >> 3) & 1) * 16;
#pragma unroll
            for (int nt = 0; nt < 8; nt++) {
                LDSM_X2(bh[nt][0], bh[nt][1], sBh + bOff + nt * 8 * ROWB);
                LDSM_X2(bl[nt][0], bl[nt][1], sBl + bOff + nt * 8 * ROWB);
            }
            const uint32_t aOff = (wm * 64 + (lane & 15)) * ROWB
                                  + ks * 32 + (lane >> 4) * 16;
#pragma unroll
            for (int mt = 0; mt < 4; mt++) {
                uint32_t ah[4], al[4];
                LDSM_X4(ah[0], ah[1], ah[2], ah[3], sAh + aOff + mt * 16 * ROWB);
                LDSM_X4(al[0], al[1], al[2], al[3], sAl + aOff + mt * 16 * ROWB);
#pragma unroll
                for (int nt = 0; nt < 8; nt++) MMA_BF16(acc[mt][nt], ah, bh[nt]);
#pragma unroll
                for (int nt = 0; nt < 8; nt++) MMA_BF16(acc[mt][nt], ah, bl[nt]);
#pragma unroll
                for (int nt = 0; nt < 8; nt++) MMA_BF16(acc[mt][nt], al, bh[nt]);
            }
        }
        __syncthreads();
    }

#pragma unroll
    for (int mt = 0; mt < 4; mt++) {
        int row0 = mBase + wm * 64 + mt * 16 + (lane >> 2);
#pragma unroll
        for (int nt = 0; nt < 8; nt++) {
            int col = nBase + wn * 64 + nt * 8 + 2 * (lane & 3);
            size_t o0 = ((size_t)row0 * N_LOCS + n) * EMB + col;
            size_t o1 = ((size_t)(row0 + 8) * N_LOCS + n) * EMB + col;
            float f0 = acc[mt][nt][0], f1 = acc[mt][nt][1];
            float f2 = acc[mt][nt][2], f3 = acc[mt][nt][3];
            float h0 = __bfloat162float(__float2bfloat16(f0));
            float h1 = __bfloat162float(__float2bfloat16(f1));
            float h2 = __bfloat162float(__float2bfloat16(f2));
            float h3 = __bfloat162float(__float2bfloat16(f3));
            *reinterpret_cast<uint32_t*>(Yh + o0) = pack2bf(f0, f1);
            *reinterpret_cast<uint32_t*>(Yl + o0) = pack2bf(f0 - h0, f1 - h1);
            *reinterpret_cast<uint32_t*>(Yh + o1) = pack2bf(f2, f3);
            *reinterpret_cast<uint32_t*>(Yl + o1) = pack2bf(f2 - h2, f3 - h3);
        }
    }
}

// ==================== stage 2: mix via HMMA (R7 config) ======================
#define BPC 4
#define MROWB 208
#define YROWB 272
#define MIX_SA   0
#define MIX_SAL  19968
#define MIX_SY   39936
#define MIX_SYL  66048
#define MIX_STAT 92160
#define MIX_SMEM 92928

__global__ __launch_bounds__(256, 2)
void mix_mma_kernel(const __nv_bfloat16* __restrict__ Yh, const __nv_bfloat16* __restrict__ Yl,
                    const float* __restrict__ bias, float* __restrict__ Z,
                    const __nv_bfloat16* __restrict__ Ahp, const __nv_bfloat16* __restrict__ Alp)
{
    extern __shared__ char smem[];
    const uint32_t sb = s2u(smem);
    const int tid = threadIdx.x, lane = tid & 31, wid = tid >> 5;
    const int wm = wid >> 2, wn = wid & 3;
    const int b0 = blockIdx.x * BPC;
    const int oBase = blockIdx.y * 128;
    float* sS  = reinterpret_cast<float*>(smem + MIX_STAT);
    float* sSS = sS + 96;

    if (tid < 192) sS[tid] = 0.f;
    for (int i = tid; i < 15 * 17; i += 256) {
        int r = 81 + i / 17, j = i % 17;
        uint4 zz = make_uint4(0, 0, 0, 0);
        *reinterpret_cast<uint4*>(smem + MIX_SY  + r * YROWB + j * 16) = zz;
        *reinterpret_cast<uint4*>(smem + MIX_SYL + r * YROWB + j * 16) = zz;
    }
    for (int i = tid; i < 1152; i += 256) {
        int r = i / 12, j = i % 12;
        cp16(sb + MIX_SA  + r * MROWB + j * 16, Ahp + r * 96 + j * 8);
        cp16(sb + MIX_SAL + r * MROWB + j * 16, Alp + r * 96 + j * 8);
    }
    for (int i = tid; i < 1296; i += 256) {
        int r = i / 16, j = i % 16;
        size_t go = ((size_t)b0 * N_LOCS + r) * EMB + oBase + j * 8;
        cp16(sb + MIX_SY  + r * YROWB + j * 16, Yh + go);
        cp16(sb + MIX_SYL + r * YROWB + j * 16, Yl + go);
    }
    cp_commit();
    cp_wait<0>();
    __syncthreads();

    for (int bb = 0; bb < BPC; bb++) {
        const int b = b0 + bb;
        if (bb > 0) {
            __syncthreads();
            for (int i = tid; i < 1296; i += 256) {
                int r = i / 16, j = i % 16;
                size_t go = ((size_t)b * N_LOCS + r) * EMB + oBase + j * 8;
                cp16(sb + MIX_SY  + r * YROWB + j * 16, Yh + go);
                cp16(sb + MIX_SYL + r * YROWB + j * 16, Yl + go);
            }
            cp_commit();
            cp_wait<0>();
            __syncthreads();
        }

        float acc[3][4][4];
#pragma unroll
        for (int mt = 0; mt < 3; mt++)
#pragma unroll
            for (int nt = 0; nt < 4; nt++)
#pragma unroll
                for (int q = 0; q < 4; q++) acc[mt][nt][q] = 0.f;

#pragma unroll
        for (int ks = 0; ks < 6; ks++) {
            uint32_t bh[4][2], bl[4][2];
            const uint32_t yOff = (uint32_t)(ks * 16 + (lane & 15)) * YROWB + wn * 64;
#pragma unroll
            for (int nt = 0; nt < 4; nt++) {
                LDSM_X2T(bh[nt][0], bh[nt][1], sb + MIX_SY  + yOff + nt * 16);
                LDSM_X2T(bl[nt][0], bl[nt][1], sb + MIX_SYL + yOff + nt * 16);
            }
            const uint32_t aOff = (uint32_t)(wm * 48 + (lane & 15)) * MROWB
                                  + ks * 32 + (lane >> 4) * 16;
#pragma unroll
            for (int mt = 0; mt < 3; mt++) {
                uint32_t ah[4], al[4];
                LDSM_X4(ah[0], ah[1], ah[2], ah[3], sb + MIX_SA  + aOff + mt * 16 * MROWB);
                LDSM_X4(al[0], al[1], al[2], al[3], sb + MIX_SAL + aOff + mt * 16 * MROWB);
#pragma unroll
                for (int nt = 0; nt < 4; nt++) {
                    MMA_BF16(acc[mt][nt], ah, bh[nt]);
                    MMA_BF16(acc[mt][nt], ah, bl[nt]);
                    MMA_BF16(acc[mt][nt], al, bh[nt]);
                }
            }
        }

        const float* bp = bias + oBase + wn * 32;
#pragma unroll
        for (int mt = 0; mt < 3; mt++) {
            int r0 = wm * 48 + mt * 16 + (lane >> 2);
            int r1 = r0 + 8;
            float s0 = 0.f, ss0 = 0.f, s1 = 0.f, ss1 = 0.f;
#pragma unroll
            for (int nt = 0; nt < 4; nt++) {
                int oc = nt * 8 + 2 * (lane & 3);
                float bb0 = __ldg(bp + oc), bb1 = __ldg(bp + oc + 1);
                float v0 = acc[mt][nt][0] + bb0, v1 = acc[mt][nt][1] + bb1;
                float v2 = acc[mt][nt][2] + bb0, v3 = acc[mt][nt][3] + bb1;
                int o = oBase + wn * 32 + oc;
                if (r0 < N_LOCS)
                    *reinterpret_cast<float2*>(&Z[((size_t)b * N_LOCS + r0) * EMB + o]) =
                        make_float2(v0, v1);
                if (r1 < N_LOCS)
                    *reinterpret_cast<float2*>(&Z[((size_t)b * N_LOCS + r1) * EMB + o]) =
                        make_float2(v2, v3);
                s0 += v0 + v1; ss0 += v0 * v0 + v1 * v1;
                s1 += v2 + v3; ss1 += v2 * v2 + v3 * v3;
            }
#pragma unroll
            for (int off = 1; off <= 2; off <<= 1) {
                s0  += __shfl_xor_sync(0xffffffffu, s0,  off);
                ss0 += __shfl_xor_sync(0xffffffffu, ss0, off);
                s1  += __shfl_xor_sync(0xffffffffu, s1,  off);
                ss1 += __shfl_xor_sync(0xffffffffu, ss1, off);
            }
            if ((lane & 3) == 0) {
                if (r0 < N_LOCS) { atomicAdd(&sS[r0], s0); atomicAdd(&sSS[r0], ss0); }
                if (r1 < N_LOCS) { atomicAdd(&sS[r1], s1); atomicAdd(&sSS[r1], ss1); }
            }
        }
    }
    __syncthreads();
    for (int m = tid; m < N_LOCS; m += 256) {
        atomicAdd(&g_sum[m],   (double)sS[m]);
        atomicAdd(&g_sumsq[m], (double)sSS[m]);
    }
}

// ==================== stats fold =============================================
__global__ void stats_kernel(const float* __restrict__ g, const float* __restrict__ be)
{
    int m = threadIdx.x;
    if (m < N_LOCS) {
        const double cnt = (double)BATCH * (double)EMB;
        double mean = g_sum[m] / cnt;
        double var  = g_sumsq[m] / cnt - mean * mean;
        if (var < 0.0) var = 0.0;
        double inv = 1.0 / sqrt(var + 1e-5);
        float sc = g[m] * (float)inv;
        g_scale[m] = sc;
        g_shift[m] = be[m] - (float)mean * sc;
        g_sum[m] = 0.0; g_sumsq[m] = 0.0;
    }
}

// ============ bn + relu (+ hi/lo residual); act out OR final fp32 out ========
__global__ __launch_bounds__(256)
void bn_relu_kernel(const float4* __restrict__ Z,
                    const __nv_bfloat16* __restrict__ Rh, const __nv_bfloat16* __restrict__ Rl,
                    float4* __restrict__ OutF,
                    __nv_bfloat16* __restrict__ Oh, __nv_bfloat16* __restrict__ Ol,
                    int sB4, int sM4)
{
    int i  = blockIdx.x * 256 + threadIdx.x;
    int o4 = i & 63, t = i >> 6;
    int bb = t / N_LOCS, m = t - bb * N_LOCS;
    float sc = g_scale[m], sh = g_shift[m];
    float4 z = Z[i];
    float4 o;
    o.x = fmaxf(fmaf(z.x, sc, sh), 0.f);
    o.y = fmaxf(fmaf(z.y, sc, sh), 0.f);
    o.z = fmaxf(fmaf(z.z, sc, sh), 0.f);
    o.w = fmaxf(fmaf(z.w, sc, sh), 0.f);
    if (Rh != nullptr) {
        uint2 RH = reinterpret_cast<const uint2*>(Rh)[i];
        uint2 RL = reinterpret_cast<const uint2*>(Rl)[i];
        __nv_bfloat162 h0 = *reinterpret_cast<__nv_bfloat162*>(&RH.x);
        __nv_bfloat162 h1 = *reinterpret_cast<__nv_bfloat162*>(&RH.y);
        __nv_bfloat162 l0 = *reinterpret_cast<__nv_bfloat162*>(&RL.x);
        __nv_bfloat162 l1 = *reinterpret_cast<__nv_bfloat162*>(&RL.y);
        o.x += __bfloat162float(h0.x) + __bfloat162float(l0.x);
        o.y += __bfloat162float(h0.y) + __bfloat162float(l0.y);
        o.z += __bfloat162float(h1.x) + __bfloat162float(l1.x);
        o.w += __bfloat162float(h1.y) + __bfloat162float(l1.y);
    }
    if (OutF != nullptr) {
        OutF[(size_t)bb * sB4 + (size_t)m * sM4 + o4] = o;
    } else {
        float hx = __bfloat162float(__float2bfloat16(o.x));
        float hy = __bfloat162float(__float2bfloat16(o.y));
        float hz = __bfloat162float(__float2bfloat16(o.z));
        float hw = __bfloat162float(__float2bfloat16(o.w));
        uint2 H, L;
        H.x = pack2bf(o.x, o.y); H.y = pack2bf(o.z, o.w);
        L.x = pack2bf(o.x - hx, o.y - hy); L.y = pack2bf(o.z - hz, o.w - hw);
        reinterpret_cast<uint2*>(Oh)[i] = H;
        reinterpret_cast<uint2*>(Ol)[i] = L;
    }
}

// ==================== weight transpose + split ===============================
__global__ void tconv_kernel(const float* __restrict__ W,
                             __nv_bfloat16* __restrict__ oh, __nv_bfloat16* __restrict__ ol,
                             int K, int Kpad)
{
    __shared__ float t[32][33];
    int nm = blockIdx.x, ob = blockIdx.y * 32, kb = blockIdx.z * 32;
    const float* Wn = W + (size_t)nm * K * EMB;
    for (int r = threadIdx.y; r < 32; r += 8) {
        int k = kb + r;
        t[r][threadIdx.x] = (k < K) ? Wn[(size_t)k * EMB + ob + threadIdx.x] : 0.f;
    }
    __syncthreads();
    size_t obase = (size_t)nm * EMB * Kpad;
    for (int r = threadIdx.y; r < 32; r += 8) {
        float v = t[threadIdx.x][r];
        __nv_bfloat16 h = __float2bfloat16(v);
        size_t d = obase + (size_t)(ob + r) * Kpad + kb + threadIdx.x;
        oh[d] = h;
        ol[d] = __float2bfloat16(v - __bfloat162float(h));
    }
}

__global__ void asplit_kernel(const float* __restrict__ A,
                              __nv_bfloat16* __restrict__ Ah, __nv_bfloat16* __restrict__ Al)
{
    int i = blockIdx.x * 256 + threadIdx.x;
    if (i < 96 * 96) {
        int m = i / 96, nn = i % 96;
        float v = (m < N_LOCS && nn < N_LOCS) ? A[m * N_LOCS + nn] : 0.f;
        __nv_bfloat16 h = __float2bfloat16(v);
        Ah[i] = h;
        Al[i] = __float2bfloat16(v - __bfloat162float(h));
    }
}

// ==================== host orchestration =====================================
static void run_stack(const float* x, int K0,
                      const float* W0, const float* b0, const float* g0, const float* be0,
                      const float* Ws, const float* bs, const float* gs, const float* bes,
                      float* bufZ, __nv_bfloat16* yh, __nv_bfloat16* yl,
                      __nv_bfloat16* acth[2], __nv_bfloat16* actl[2],
                      __nv_bfloat16* wth, __nv_bfloat16* wtl,
                      __nv_bfloat16* w0h, __nv_bfloat16* w0l,
                      __nv_bfloat16* Ah96, __nv_bfloat16* Al96, float* outF)
{
    dim3 tcb(32, 8);
    tconv_kernel<<<dim3(N_LOCS, 8, 2), tcb>>>(W0, w0h, w0l, K0, 64);
    tconv_kernel<<<dim3(7 * N_LOCS, 8, 8), tcb>>>(Ws, wth, wtl, EMB, EMB);

    const dim3 gG0(BATCH / 128, EMB / 128, N_LOCS);
    const dim3 gG(BATCH / 256, EMB / 128, N_LOCS);
    const dim3 gMix(BATCH / BPC, 2);
    const int  gNorm = ELEMS / 4 / 256;

    gemm0_kernel<<<gG0, 256, GEMM_SMEM>>>(x, w0h, w0l, yh, yl, K0, 64);
    mix_mma_kernel<<<gMix, 256, MIX_SMEM>>>(yh, yl, b0, bufZ, Ah96, Al96);
    stats_kernel<<<1, N_LOCS>>>(g0, be0);
    bn_relu_kernel<<<gNorm, 256>>>((const float4*)bufZ, nullptr, nullptr,
                                   nullptr, acth[1], actl[1], 0, 0);

    for (int bi = 1; bi <= 7; bi++) {
        int i = bi - 1, r = bi & 1, w = (bi + 1) & 1;
        gemm_mma_kernel<<<gG, 256, GEMM2_SMEM>>>(
            acth[r], actl[r],
            wth + (size_t)i * N_LOCS * EMB * EMB, wtl + (size_t)i * N_LOCS * EMB * EMB,
            yh, yl);
        mix_mma_kernel<<<gMix, 256, MIX_SMEM>>>(yh, yl, bs + (size_t)i * EMB, bufZ,
                                                Ah96, Al96);
        stats_kernel<<<1, N_LOCS>>>(gs + (size_t)i * N_LOCS, bes + (size_t)i * N_LOCS);
        if (bi == 7)
            bn_relu_kernel<<<gNorm, 256>>>((const float4*)bufZ, acth[r], actl[r],
                                           (float4*)outF, nullptr, nullptr,
                                           N_LOCS * 128, 128);
        else
            bn_relu_kernel<<<gNorm, 256>>>((const float4*)bufZ, acth[r], actl[r],
                                           nullptr, acth[w], actl[w], 0, 0);
    }
}

extern "C" void kernel_launch(void* const* d_in, const int* in_sizes, int n_in,
                              void* d_out, int out_size)
{
    (void)in_sizes; (void)n_in; (void)out_size;
    const float* x_bo   = (const float*)d_in[0];
    const float* x_po   = (const float*)d_in[1];
    const float* A      = (const float*)d_in[2];
    const float* W0_bo  = (const float*)d_in[3];
    const float* b0_bo  = (const float*)d_in[4];
    const float* g0_bo  = (const float*)d_in[5];
    const float* be0_bo = (const float*)d_in[6];
    const float* W_bo   = (const float*)d_in[7];
    const float* b_bo   = (const float*)d_in[8];
    const float* g_bo   = (const float*)d_in[9];
    const float* be_bo  = (const float*)d_in[10];
    const float* W0_po  = (const float*)d_in[11];
    const float* b0_po  = (const float*)d_in[12];
    const float* g0_po  = (const float*)d_in[13];
    const float* be0_po = (const float*)d_in[14];
    const float* W_po   = (const float*)d_in[15];
    const float* b_po   = (const float*)d_in[16];
    const float* g_po   = (const float*)d_in[17];
    const float* be_po  = (const float*)d_in[18];
    float* out = (float*)d_out;

    cudaFuncSetAttribute(gemm0_kernel,
                         cudaFuncAttributeMaxDynamicSharedMemorySize, GEMM_SMEM);
    cudaFuncSetAttribute(gemm_mma_kernel,
                         cudaFuncAttributeMaxDynamicSharedMemorySize, GEMM2_SMEM);
    cudaFuncSetAttribute(mix_mma_kernel,
                         cudaFuncAttributeMaxDynamicSharedMemorySize, MIX_SMEM);

    float *bufZ;
    __nv_bfloat16 *yh, *yl, *wth, *wtl, *w0h, *w0l, *Ah96, *Al96;
    __nv_bfloat16 *acth[2], *actl[2];
    cudaGetSymbolAddress((void**)&bufZ, g_bufZ);
    cudaGetSymbolAddress((void**)&yh, g_yh);
    cudaGetSymbolAddress((void**)&yl, g_yl);
    cudaGetSymbolAddress((void**)&acth[0], g_ah0);
    cudaGetSymbolAddress((void**)&actl[0], g_al0);
    cudaGetSymbolAddress((void**)&acth[1], g_ah1);
    cudaGetSymbolAddress((void**)&actl[1], g_al1);
    cudaGetSymbolAddress((void**)&wth, g_wth);
    cudaGetSymbolAddress((void**)&wtl, g_wtl);
    cudaGetSymbolAddress((void**)&w0h, g_w0h);
    cudaGetSymbolAddress((void**)&w0l, g_w0l);
    cudaGetSymbolAddress((void**)&Ah96, g_Ah96);
    cudaGetSymbolAddress((void**)&Al96, g_Al96);

    asplit_kernel<<<36, 256>>>(A, Ah96, Al96);

    run_stack(x_bo, 35, W0_bo, b0_bo, g0_bo, be0_bo, W_bo, b_bo, g_bo, be_bo,
              bufZ, yh, yl, acth, actl, wth, wtl, w0h, w0l, Ah96, Al96, out);
    run_stack(x_po, 40, W0_po, b0_po, g0_po, be0_po, W_po, b_po, g_po, be_po,
              bufZ, yh, yl, acth, actl, wth, wtl, w0h, w0l, Ah96, Al96, out + EMB);
}

// round 14
// speedup vs baseline: 1.1654x; 1.1654x over previous
#include <cuda_runtime.h>
#include <cuda_bf16.h>
#include <cstdint>
#include <cstddef>

#define N_LOCS 81
#define BATCH  2048
#define EMB    256
#define ELEMS  (BATCH * N_LOCS * EMB)
#define WS_ELEMS (7 * N_LOCS * EMB * EMB)
#define W0_ELEMS (N_LOCS * EMB * 64)

// ---- per-stack scratch (index 0 = board, 1 = prev-orders) ----
__device__ float  g_bufZ[2][ELEMS];
__device__ __nv_bfloat16 g_yh[2][ELEMS];
__device__ __nv_bfloat16 g_yl[2][ELEMS];
__device__ __nv_bfloat16 g_a0h[2][ELEMS];
__device__ __nv_bfloat16 g_a0l[2][ELEMS];
__device__ __nv_bfloat16 g_a1h[2][ELEMS];
__device__ __nv_bfloat16 g_a1l[2][ELEMS];
__device__ __nv_bfloat16 g_wth[2][WS_ELEMS];
__device__ __nv_bfloat16 g_wtl[2][WS_ELEMS];
__device__ __nv_bfloat16 g_w0h[2][W0_ELEMS];
__device__ __nv_bfloat16 g_w0l[2][W0_ELEMS];
__device__ double g_sum[2][N_LOCS];
__device__ double g_sumsq[2][N_LOCS];
__device__ float  g_scale[2][N_LOCS];
__device__ float  g_shift[2][N_LOCS];
__device__ __nv_bfloat16 g_Ah96[96 * 96];
__device__ __nv_bfloat16 g_Al96[96 * 96];

__device__ __forceinline__ uint32_t s2u(const void* p) {
    uint32_t a;
    asm("{ .reg .u64 t; cvta.to.shared.u64 t, %1; cvt.u32.u64 %0, t; }" : "=r"(a) : "l"(p));
    return a;
}
__device__ __forceinline__ void cp16(uint32_t s, const void* g) {
    asm volatile("cp.async.cg.shared.global [%0], [%1], 16;" :: "r"(s), "l"(g) : "memory");
}
__device__ __forceinline__ void cp_commit() {
    asm volatile("cp.async.commit_group;" ::: "memory");
}
template <int N>
__device__ __forceinline__ void cp_wait() {
    asm volatile("cp.async.wait_group %0;" :: "n"(N) : "memory");
}
#define LDSM_X4(r0, r1, r2, r3, addr) \
    asm volatile("ldmatrix.sync.aligned.m8n8.x4.shared.b16 {%0,%1,%2,%3}, [%4];" \
                 : "=r"(r0), "=r"(r1), "=r"(r2), "=r"(r3) : "r"(addr))
#define LDSM_X2(r0, r1, addr) \
    asm volatile("ldmatrix.sync.aligned.m8n8.x2.shared.b16 {%0,%1}, [%2];" \
                 : "=r"(r0), "=r"(r1) : "r"(addr))
#define LDSM_X2T(r0, r1, addr) \
    asm volatile("ldmatrix.sync.aligned.m8n8.x2.trans.shared.b16 {%0,%1}, [%2];" \
                 : "=r"(r0), "=r"(r1) : "r"(addr))
#define MMA_BF16(d, a, b) \
    asm volatile("mma.sync.aligned.m16n8k16.row.col.f32.bf16.bf16.f32 " \
                 "{%0,%1,%2,%3}, {%4,%5,%6,%7}, {%8,%9}, {%0,%1,%2,%3};" \
                 : "+f"((d)[0]), "+f"((d)[1]), "+f"((d)[2]), "+f"((d)[3]) \
                 : "r"((a)[0]), "r"((a)[1]), "r"((a)[2]), "r"((a)[3]), \
                   "r"((b)[0]), "r"((b)[1]))

__device__ __forceinline__ uint32_t pack2bf(float a, float b) {
    __nv_bfloat162 t;
    t.x = __float2bfloat16(a); t.y = __float2bfloat16(b);
    return *reinterpret_cast<uint32_t*>(&t);
}

#define ROWB   80
#define TILE_B 10240
#define STAGE_B 40960
#define GEMM_SMEM (2 * STAGE_B)

// =================== shared MMA core (R7) =====================================
struct GemmCtx {
    uint32_t sb;
    int tid, wid, lane, wm, wn;
};

__device__ __forceinline__ void gemm_compute_stage(const GemmCtx& g, int c,
                                                   float acc[4][4][4])
{
    const uint32_t st  = g.sb + (c & 1) * STAGE_B;
    const uint32_t sAh = st;
    const uint32_t sAl = st + TILE_B;
    const uint32_t sBh = st + 2 * TILE_B;
    const uint32_t sBl = st + 3 * TILE_B;
#pragma unroll
    for (int ks = 0; ks < 2; ks++) {
        uint32_t bh[4][2], bl[4][2];
        const uint32_t bOff = (g.wn * 32 + (g.lane & 7)) * ROWB
                              + ks * 32 + ((g.lane >> 3) & 1) * 16;
#pragma unroll
        for (int nt = 0; nt < 4; nt++) {
            LDSM_X2(bh[nt][0], bh[nt][1], sBh + bOff + nt * 8 * ROWB);
            LDSM_X2(bl[nt][0], bl[nt][1], sBl + bOff + nt * 8 * ROWB);
        }
        const uint32_t aOff = (g.wm * 64 + (g.lane & 15)) * ROWB
                              + ks * 32 + (g.lane >> 4) * 16;
#pragma unroll
        for (int mt = 0; mt < 4; mt++) {
            uint32_t ah[4], al[4];
            LDSM_X4(ah[0], ah[1], ah[2], ah[3], sAh + aOff + mt * 16 * ROWB);
            LDSM_X4(al[0], al[1], al[2], al[3], sAl + aOff + mt * 16 * ROWB);
#pragma unroll
            for (int nt = 0; nt < 4; nt++) {
                MMA_BF16(acc[mt][nt], ah, bh[nt]);
                MMA_BF16(acc[mt][nt], ah, bl[nt]);
                MMA_BF16(acc[mt][nt], al, bh[nt]);
            }
        }
    }
}

__device__ __forceinline__ void gemm_epilogue(const GemmCtx& g, float acc[4][4][4],
                                              int mBase, int nBase, int n,
                                              __nv_bfloat16* Yh, __nv_bfloat16* Yl)
{
#pragma unroll
    for (int mt = 0; mt < 4; mt++) {
        int row0 = mBase + g.wm * 64 + mt * 16 + (g.lane >> 2);
#pragma unroll
        for (int nt = 0; nt < 4; nt++) {
            int col = nBase + g.wn * 32 + nt * 8 + 2 * (g.lane & 3);
            size_t o0 = ((size_t)row0 * N_LOCS + n) * EMB + col;
            size_t o1 = ((size_t)(row0 + 8) * N_LOCS + n) * EMB + col;
            float f0 = acc[mt][nt][0], f1 = acc[mt][nt][1];
            float f2 = acc[mt][nt][2], f3 = acc[mt][nt][3];
            float h0 = __bfloat162float(__float2bfloat16(f0));
            float h1 = __bfloat162float(__float2bfloat16(f1));
            float h2 = __bfloat162float(__float2bfloat16(f2));
            float h3 = __bfloat162float(__float2bfloat16(f3));
            *reinterpret_cast<uint32_t*>(Yh + o0) = pack2bf(f0, f1);
            *reinterpret_cast<uint32_t*>(Yl + o0) = pack2bf(f0 - h0, f1 - h1);
            *reinterpret_cast<uint32_t*>(Yh + o1) = pack2bf(f2, f3);
            *reinterpret_cast<uint32_t*>(Yl + o1) = pack2bf(f2 - h2, f3 - h3);
        }
    }
}

// ============ stage 1a: block-0 GEMM (raw fp32 x, split in-register) =========
__global__ __launch_bounds__(256, 2)
void gemm0_kernel(const float* __restrict__ X,
                  const __nv_bfloat16* __restrict__ Wh, const __nv_bfloat16* __restrict__ Wl,
                  __nv_bfloat16* __restrict__ Yh, __nv_bfloat16* __restrict__ Yl,
                  int K, int Kpad)
{
    extern __shared__ char smem[];
    GemmCtx g;
    g.sb = s2u(smem); g.tid = threadIdx.x; g.wid = g.tid >> 5; g.lane = g.tid & 31;
    g.wm = g.wid >> 2; g.wn = g.wid & 3;
    const int n = blockIdx.z, mBase = blockIdx.x * 128, nBase = blockIdx.y * 128;
    const int ldx = N_LOCS * K;
    const float* Xn = X + (size_t)n * K;
    const __nv_bfloat16* Whn = Wh + (size_t)n * EMB * Kpad;
    const __nv_bfloat16* Wln = Wl + (size_t)n * EMB * Kpad;

    float acc[4][4][4];
#pragma unroll
    for (int mt = 0; mt < 4; mt++)
#pragma unroll
        for (int nt = 0; nt < 4; nt++)
#pragma unroll
            for (int q = 0; q < 4; q++) acc[mt][nt][q] = 0.f;

    const int nchunk = Kpad >> 5;

    auto load_chunk = [&](int c) {
        const uint32_t stOff = (c & 1) * STAGE_B;
        const int k0 = c << 5;
        for (int it = 0; it < 16; it++) {
            int idx = g.tid + (it << 8);
            int r = idx >> 5, kk = idx & 31;
            int k = k0 + kk;
            float v = (k < K) ? Xn[(size_t)(mBase + r) * ldx + k] : 0.f;
            float h = __bfloat162float(__float2bfloat16(v));
            uint32_t so = stOff + r * ROWB + kk * 2;
            *reinterpret_cast<__nv_bfloat16*>(smem + so)          = __float2bfloat16(v);
            *reinterpret_cast<__nv_bfloat16*>(smem + so + TILE_B) = __float2bfloat16(v - h);
        }
#pragma unroll
        for (int it = 0; it < 2; it++) {
            int idx = g.tid + (it << 8);
            int r = idx >> 2, j = idx & 3;
            size_t go = (size_t)(nBase + r) * Kpad + k0 + j * 8;
            uint32_t so = g.sb + stOff + 2 * TILE_B + r * ROWB + j * 16;
            cp16(so,          Whn + go);
            cp16(so + TILE_B, Wln + go);
        }
        cp_commit();
    };

    load_chunk(0);
    for (int c = 0; c < nchunk; c++) {
        if (c + 1 < nchunk) { load_chunk(c + 1); cp_wait<1>(); }
        else                { cp_wait<0>(); }
        __syncthreads();
        gemm_compute_stage(g, c, acc);
        __syncthreads();
    }
    gemm_epilogue(g, acc, mBase, nBase, n, Yh, Yl);
}

// ============ stage 1b: GEMM, act hi/lo input (pure cp.async, R7) ============
__global__ __launch_bounds__(256, 2)
void gemm_mma_kernel(const __nv_bfloat16* __restrict__ Xh, const __nv_bfloat16* __restrict__ Xl,
                     const __nv_bfloat16* __restrict__ Wh, const __nv_bfloat16* __restrict__ Wl,
                     __nv_bfloat16* __restrict__ Yh, __nv_bfloat16* __restrict__ Yl)
{
    extern __shared__ char smem[];
    GemmCtx g;
    g.sb = s2u(smem); g.tid = threadIdx.x; g.wid = g.tid >> 5; g.lane = g.tid & 31;
    g.wm = g.wid >> 2; g.wn = g.wid & 3;
    const int n = blockIdx.z, mBase = blockIdx.x * 128, nBase = blockIdx.y * 128;
    const int ldx = N_LOCS * EMB;
    const __nv_bfloat16* Xhn = Xh + (size_t)n * EMB;
    const __nv_bfloat16* Xln = Xl + (size_t)n * EMB;
    const __nv_bfloat16* Whn = Wh + (size_t)n * EMB * EMB;
    const __nv_bfloat16* Wln = Wl + (size_t)n * EMB * EMB;

    float acc[4][4][4];
#pragma unroll
    for (int mt = 0; mt < 4; mt++)
#pragma unroll
        for (int nt = 0; nt < 4; nt++)
#pragma unroll
            for (int q = 0; q < 4; q++) acc[mt][nt][q] = 0.f;

    auto load_chunk = [&](int c) {
        const uint32_t st = g.sb + (c & 1) * STAGE_B;
        const int k0 = c << 5;
#pragma unroll
        for (int it = 0; it < 2; it++) {
            int idx = g.tid + (it << 8);
            int r = idx >> 2, j = idx & 3;
            size_t go = (size_t)(mBase + r) * ldx + k0 + j * 8;
            uint32_t so = st + r * ROWB + j * 16;
            cp16(so,          Xhn + go);
            cp16(so + TILE_B, Xln + go);
        }
#pragma unroll
        for (int it = 0; it < 2; it++) {
            int idx = g.tid + (it << 8);
            int r = idx >> 2, j = idx & 3;
            size_t go = (size_t)(nBase + r) * EMB + k0 + j * 8;
            uint32_t so = st + 2 * TILE_B + r * ROWB + j * 16;
            cp16(so,          Whn + go);
            cp16(so + TILE_B, Wln + go);
        }
        cp_commit();
    };

    load_chunk(0);
#pragma unroll 1
    for (int c = 0; c < 8; c++) {
        if (c + 1 < 8) { load_chunk(c + 1); cp_wait<1>(); }
        else           { cp_wait<0>(); }
        __syncthreads();
        gemm_compute_stage(g, c, acc);
        __syncthreads();
    }
    gemm_epilogue(g, acc, mBase, nBase, n, Yh, Yl);
}

// ==================== stage 2: mix via HMMA (R7 config) ======================
#define BPC 4
#define MROWB 208
#define YROWB 272
#define MIX_SA   0
#define MIX_SAL  19968
#define MIX_SY   39936
#define MIX_SYL  66048
#define MIX_STAT 92160
#define MIX_SMEM 92928

__global__ __launch_bounds__(256, 2)
void mix_mma_kernel(const __nv_bfloat16* __restrict__ Yh, const __nv_bfloat16* __restrict__ Yl,
                    const float* __restrict__ bias, float* __restrict__ Z,
                    const __nv_bfloat16* __restrict__ Ahp, const __nv_bfloat16* __restrict__ Alp,
                    double* __restrict__ gsum, double* __restrict__ gsumsq)
{
    extern __shared__ char smem[];
    const uint32_t sb = s2u(smem);
    const int tid = threadIdx.x, lane = tid & 31, wid = tid >> 5;
    const int wm = wid >> 2, wn = wid & 3;
    const int b0 = blockIdx.x * BPC;
    const int oBase = blockIdx.y * 128;
    float* sS  = reinterpret_cast<float*>(smem + MIX_STAT);
    float* sSS = sS + 96;

    if (tid < 192) sS[tid] = 0.f;
    for (int i = tid; i < 15 * 17; i += 256) {
        int r = 81 + i / 17, j = i % 17;
        uint4 zz = make_uint4(0, 0, 0, 0);
        *reinterpret_cast<uint4*>(smem + MIX_SY  + r * YROWB + j * 16) = zz;
        *reinterpret_cast<uint4*>(smem + MIX_SYL + r * YROWB + j * 16) = zz;
    }
    for (int i = tid; i < 1152; i += 256) {
        int r = i / 12, j = i % 12;
        cp16(sb + MIX_SA  + r * MROWB + j * 16, Ahp + r * 96 + j * 8);
        cp16(sb + MIX_SAL + r * MROWB + j * 16, Alp + r * 96 + j * 8);
    }
    for (int i = tid; i < 1296; i += 256) {
        int r = i / 16, j = i % 16;
        size_t go = ((size_t)b0 * N_LOCS + r) * EMB + oBase + j * 8;
        cp16(sb + MIX_SY  + r * YROWB + j * 16, Yh + go);
        cp16(sb + MIX_SYL + r * YROWB + j * 16, Yl + go);
    }
    cp_commit();
    cp_wait<0>();
    __syncthreads();

    for (int bb = 0; bb < BPC; bb++) {
        const int b = b0 + bb;
        if (bb > 0) {
            __syncthreads();
            for (int i = tid; i < 1296; i += 256) {
                int r = i / 16, j = i % 16;
                size_t go = ((size_t)b * N_LOCS + r) * EMB + oBase + j * 8;
                cp16(sb + MIX_SY  + r * YROWB + j * 16, Yh + go);
                cp16(sb + MIX_SYL + r * YROWB + j * 16, Yl + go);
            }
            cp_commit();
            cp_wait<0>();
            __syncthreads();
        }

        float acc[3][4][4];
#pragma unroll
        for (int mt = 0; mt < 3; mt++)
#pragma unroll
            for (int nt = 0; nt < 4; nt++)
#pragma unroll
                for (int q = 0; q < 4; q++) acc[mt][nt][q] = 0.f;

#pragma unroll
        for (int ks = 0; ks < 6; ks++) {
            uint32_t bh[4][2], bl[4][2];
            const uint32_t yOff = (uint32_t)(ks * 16 + (lane & 15)) * YROWB + wn * 64;
#pragma unroll
            for (int nt = 0; nt < 4; nt++) {
                LDSM_X2T(bh[nt][0], bh[nt][1], sb + MIX_SY  + yOff + nt * 16);
                LDSM_X2T(bl[nt][0], bl[nt][1], sb + MIX_SYL + yOff + nt * 16);
            }
            const uint32_t aOff = (uint32_t)(wm * 48 + (lane & 15)) * MROWB
                                  + ks * 32 + (lane >> 4) * 16;
#pragma unroll
            for (int mt = 0; mt < 3; mt++) {
                uint32_t ah[4], al[4];
                LDSM_X4(ah[0], ah[1], ah[2], ah[3], sb + MIX_SA  + aOff + mt * 16 * MROWB);
                LDSM_X4(al[0], al[1], al[2], al[3], sb + MIX_SAL + aOff + mt * 16 * MROWB);
#pragma unroll
                for (int nt = 0; nt < 4; nt++) {
                    MMA_BF16(acc[mt][nt], ah, bh[nt]);
                    MMA_BF16(acc[mt][nt], ah, bl[nt]);
                    MMA_BF16(acc[mt][nt], al, bh[nt]);
                }
            }
        }

        const float* bp = bias + oBase + wn * 32;
#pragma unroll
        for (int mt = 0; mt < 3; mt++) {
            int r0 = wm * 48 + mt * 16 + (lane >> 2);
            int r1 = r0 + 8;
            float s0 = 0.f, ss0 = 0.f, s1 = 0.f, ss1 = 0.f;
#pragma unroll
            for (int nt = 0; nt < 4; nt++) {
                int oc = nt * 8 + 2 * (lane & 3);
                float bb0 = __ldg(bp + oc), bb1 = __ldg(bp + oc + 1);
                float v0 = acc[mt][nt][0] + bb0, v1 = acc[mt][nt][1] + bb1;
                float v2 = acc[mt][nt][2] + bb0, v3 = acc[mt][nt][3] + bb1;
                int o = oBase + wn * 32 + oc;
                if (r0 < N_LOCS)
                    *reinterpret_cast<float2*>(&Z[((size_t)b * N_LOCS + r0) * EMB + o]) =
                        make_float2(v0, v1);
                if (r1 < N_LOCS)
                    *reinterpret_cast<float2*>(&Z[((size_t)b * N_LOCS + r1) * EMB + o]) =
                        make_float2(v2, v3);
                s0 += v0 + v1; ss0 += v0 * v0 + v1 * v1;
                s1 += v2 + v3; ss1 += v2 * v2 + v3 * v3;
            }
#pragma unroll
            for (int off = 1; off <= 2; off <<= 1) {
                s0  += __shfl_xor_sync(0xffffffffu, s0,  off);
                ss0 += __shfl_xor_sync(0xffffffffu, ss0, off);
                s1  += __shfl_xor_sync(0xffffffffu, s1,  off);
                ss1 += __shfl_xor_sync(0xffffffffu, ss1, off);
            }
            if ((lane & 3) == 0) {
                if (r0 < N_LOCS) { atomicAdd(&sS[r0], s0); atomicAdd(&sSS[r0], ss0); }
                if (r1 < N_LOCS) { atomicAdd(&sS[r1], s1); atomicAdd(&sSS[r1], ss1); }
            }
        }
    }
    __syncthreads();
    for (int m = tid; m < N_LOCS; m += 256) {
        atomicAdd(&gsum[m],   (double)sS[m]);
        atomicAdd(&gsumsq[m], (double)sSS[m]);
    }
}

// ==================== stats fold (per-stack pointers) ========================
__global__ void stats_kernel(const float* __restrict__ g, const float* __restrict__ be,
                             double* __restrict__ gsum, double* __restrict__ gsumsq,
                             float* __restrict__ gscale, float* __restrict__ gshift)
{
    int m = threadIdx.x;
    if (m < N_LOCS) {
        const double cnt = (double)BATCH * (double)EMB;
        double mean = gsum[m] / cnt;
        double var  = gsumsq[m] / cnt - mean * mean;
        if (var < 0.0) var = 0.0;
        double inv = 1.0 / sqrt(var + 1e-5);
        float sc = g[m] * (float)inv;
        gscale[m] = sc;
        gshift[m] = be[m] - (float)mean * sc;
        gsum[m] = 0.0; gsumsq[m] = 0.0;
    }
}

// ============ bn + relu (+ hi/lo residual); act out OR final fp32 out ========
__global__ __launch_bounds__(256)
void bn_relu_kernel(const float4* __restrict__ Z,
                    const __nv_bfloat16* __restrict__ Rh, const __nv_bfloat16* __restrict__ Rl,
                    float4* __restrict__ OutF,
                    __nv_bfloat16* __restrict__ Oh, __nv_bfloat16* __restrict__ Ol,
                    int sB4, int sM4,
                    const float* __restrict__ gscale, const float* __restrict__ gshift)
{
    int i  = blockIdx.x * 256 + threadIdx.x;
    int o4 = i & 63, t = i >> 6;
    int bb = t / N_LOCS, m = t - bb * N_LOCS;
    float sc = gscale[m], sh = gshift[m];
    float4 z = Z[i];
    float4 o;
    o.x = fmaxf(fmaf(z.x, sc, sh), 0.f);
    o.y = fmaxf(fmaf(z.y, sc, sh), 0.f);
    o.z = fmaxf(fmaf(z.z, sc, sh), 0.f);
    o.w = fmaxf(fmaf(z.w, sc, sh), 0.f);
    if (Rh != nullptr) {
        uint2 RH = reinterpret_cast<const uint2*>(Rh)[i];
        uint2 RL = reinterpret_cast<const uint2*>(Rl)[i];
        __nv_bfloat162 h0 = *reinterpret_cast<__nv_bfloat162*>(&RH.x);
        __nv_bfloat162 h1 = *reinterpret_cast<__nv_bfloat162*>(&RH.y);
        __nv_bfloat162 l0 = *reinterpret_cast<__nv_bfloat162*>(&RL.x);
        __nv_bfloat162 l1 = *reinterpret_cast<__nv_bfloat162*>(&RL.y);
        o.x += __bfloat162float(h0.x) + __bfloat162float(l0.x);
        o.y += __bfloat162float(h0.y) + __bfloat162float(l0.y);
        o.z += __bfloat162float(h1.x) + __bfloat162float(l1.x);
        o.w += __bfloat162float(h1.y) + __bfloat162float(l1.y);
    }
    if (OutF != nullptr) {
        OutF[(size_t)bb * sB4 + (size_t)m * sM4 + o4] = o;
    } else {
        float hx = __bfloat162float(__float2bfloat16(o.x));
        float hy = __bfloat162float(__float2bfloat16(o.y));
        float hz = __bfloat162float(__float2bfloat16(o.z));
        float hw = __bfloat162float(__float2bfloat16(o.w));
        uint2 H, L;
        H.x = pack2bf(o.x, o.y); H.y = pack2bf(o.z, o.w);
        L.x = pack2bf(o.x - hx, o.y - hy); L.y = pack2bf(o.z - hz, o.w - hw);
        reinterpret_cast<uint2*>(Oh)[i] = H;
        reinterpret_cast<uint2*>(Ol)[i] = L;
    }
}

// ==================== weight transpose + split ===============================
__global__ void tconv_kernel(const float* __restrict__ W,
                             __nv_bfloat16* __restrict__ oh, __nv_bfloat16* __restrict__ ol,
                             int K, int Kpad)
{
    __shared__ float t[32][33];
    int nm = blockIdx.x, ob = blockIdx.y * 32, kb = blockIdx.z * 32;
    const float* Wn = W + (size_t)nm * K * EMB;
    for (int r = threadIdx.y; r < 32; r += 8) {
        int k = kb + r;
        t[r][threadIdx.x] = (k < K) ? Wn[(size_t)k * EMB + ob + threadIdx.x] : 0.f;
    }
    __syncthreads();
    size_t obase = (size_t)nm * EMB * Kpad;
    for (int r = threadIdx.y; r < 32; r += 8) {
        float v = t[threadIdx.x][r];
        __nv_bfloat16 h = __float2bfloat16(v);
        size_t d = obase + (size_t)(ob + r) * Kpad + kb + threadIdx.x;
        oh[d] = h;
        ol[d] = __float2bfloat16(v - __bfloat162float(h));
    }
}

__global__ void asplit_kernel(const float* __restrict__ A,
                              __nv_bfloat16* __restrict__ Ah, __nv_bfloat16* __restrict__ Al)
{
    int i = blockIdx.x * 256 + threadIdx.x;
    if (i < 96 * 96) {
        int m = i / 96, nn = i % 96;
        float v = (m < N_LOCS && nn < N_LOCS) ? A[m * N_LOCS + nn] : 0.f;
        __nv_bfloat16 h = __float2bfloat16(v);
        Ah[i] = h;
        Al[i] = __float2bfloat16(v - __bfloat162float(h));
    }
}

// ==================== host orchestration =====================================
struct StackPtrs {
    float* bufZ;
    __nv_bfloat16 *yh, *yl, *a0h, *a0l, *a1h, *a1l, *wth, *wtl, *w0h, *w0l;
    double *sum, *sumsq;
    float *scale, *shift;
};

static void run_stack(cudaStream_t st, const float* x, int K0,
                      const float* W0, const float* b0, const float* g0, const float* be0,
                      const float* Ws, const float* bs, const float* gs, const float* bes,
                      const StackPtrs& p,
                      __nv_bfloat16* Ah96, __nv_bfloat16* Al96, float* outF)
{
    dim3 tcb(32, 8);
    tconv_kernel<<<dim3(N_LOCS, 8, 2), tcb, 0, st>>>(W0, p.w0h, p.w0l, K0, 64);
    tconv_kernel<<<dim3(7 * N_LOCS, 8, 8), tcb, 0, st>>>(Ws, p.wth, p.wtl, EMB, EMB);

    const dim3 gG(BATCH / 128, EMB / 128, N_LOCS);
    const dim3 gMix(BATCH / BPC, 2);
    const int  gNorm = ELEMS / 4 / 256;

    __nv_bfloat16* acth[2] = { p.a0h, p.a1h };
    __nv_bfloat16* actl[2] = { p.a0l, p.a1l };

    gemm0_kernel<<<gG, 256, GEMM_SMEM, st>>>(x, p.w0h, p.w0l, p.yh, p.yl, K0, 64);
    mix_mma_kernel<<<gMix, 256, MIX_SMEM, st>>>(p.yh, p.yl, b0, p.bufZ, Ah96, Al96,
                                                p.sum, p.sumsq);
    stats_kernel<<<1, N_LOCS, 0, st>>>(g0, be0, p.sum, p.sumsq, p.scale, p.shift);
    bn_relu_kernel<<<gNorm, 256, 0, st>>>((const float4*)p.bufZ, nullptr, nullptr,
                                          nullptr, acth[1], actl[1], 0, 0,
                                          p.scale, p.shift);

    for (int bi = 1; bi <= 7; bi++) {
        int i = bi - 1, r = bi & 1, w = (bi + 1) & 1;
        gemm_mma_kernel<<<gG, 256, GEMM_SMEM, st>>>(
            acth[r], actl[r],
            p.wth + (size_t)i * N_LOCS * EMB * EMB, p.wtl + (size_t)i * N_LOCS * EMB * EMB,
            p.yh, p.yl);
        mix_mma_kernel<<<gMix, 256, MIX_SMEM, st>>>(p.yh, p.yl, bs + (size_t)i * EMB,
                                                    p.bufZ, Ah96, Al96, p.sum, p.sumsq);
        stats_kernel<<<1, N_LOCS, 0, st>>>(gs + (size_t)i * N_LOCS, bes + (size_t)i * N_LOCS,
                                           p.sum, p.sumsq, p.scale, p.shift);
        if (bi == 7)
            bn_relu_kernel<<<gNorm, 256, 0, st>>>((const float4*)p.bufZ, acth[r], actl[r],
                                                  (float4*)outF, nullptr, nullptr,
                                                  N_LOCS * 128, 128, p.scale, p.shift);
        else
            bn_relu_kernel<<<gNorm, 256, 0, st>>>((const float4*)p.bufZ, acth[r], actl[r],
                                                  nullptr, acth[w], actl[w], 0, 0,
                                                  p.scale, p.shift);
    }
}

static StackPtrs get_ptrs(int s)
{
    StackPtrs p;
    char* base;
    cudaGetSymbolAddress((void**)&base, g_bufZ);
    p.bufZ = (float*)base + (size_t)s * ELEMS;
    cudaGetSymbolAddress((void**)&base, g_yh);  p.yh  = (__nv_bfloat16*)base + (size_t)s * ELEMS;
    cudaGetSymbolAddress((void**)&base, g_yl);  p.yl  = (__nv_bfloat16*)base + (size_t)s * ELEMS;
    cudaGetSymbolAddress((void**)&base, g_a0h); p.a0h = (__nv_bfloat16*)base + (size_t)s * ELEMS;
    cudaGetSymbolAddress((void**)&base, g_a0l); p.a0l = (__nv_bfloat16*)base + (size_t)s * ELEMS;
    cudaGetSymbolAddress((void**)&base, g_a1h); p.a1h = (__nv_bfloat16*)base + (size_t)s * ELEMS;
    cudaGetSymbolAddress((void**)&base, g_a1l); p.a1l = (__nv_bfloat16*)base + (size_t)s * ELEMS;
    cudaGetSymbolAddress((void**)&base, g_wth); p.wth = (__nv_bfloat16*)base + (size_t)s * WS_ELEMS;
    cudaGetSymbolAddress((void**)&base, g_wtl); p.wtl = (__nv_bfloat16*)base + (size_t)s * WS_ELEMS;
    cudaGetSymbolAddress((void**)&base, g_w0h); p.w0h = (__nv_bfloat16*)base + (size_t)s * W0_ELEMS;
    cudaGetSymbolAddress((void**)&base, g_w0l); p.w0l = (__nv_bfloat16*)base + (size_t)s * W0_ELEMS;
    cudaGetSymbolAddress((void**)&base, g_sum);   p.sum   = (double*)base + (size_t)s * N_LOCS;
    cudaGetSymbolAddress((void**)&base, g_sumsq); p.sumsq = (double*)base + (size_t)s * N_LOCS;
    cudaGetSymbolAddress((void**)&base, g_scale); p.scale = (float*)base + (size_t)s * N_LOCS;
    cudaGetSymbolAddress((void**)&base, g_shift); p.shift = (float*)base + (size_t)s * N_LOCS;
    return p;
}

extern "C" void kernel_launch(void* const* d_in, const int* in_sizes, int n_in,
                              void* d_out, int out_size)
{
    (void)in_sizes; (void)n_in; (void)out_size;
    const float* x_bo   = (const float*)d_in[0];
    const float* x_po   = (const float*)d_in[1];
    const float* A      = (const float*)d_in[2];
    const float* W0_bo  = (const float*)d_in[3];
    const float* b0_bo  = (const float*)d_in[4];
    const float* g0_bo  = (const float*)d_in[5];
    const float* be0_bo = (const float*)d_in[6];
    const float* W_bo   = (const float*)d_in[7];
    const float* b_bo   = (const float*)d_in[8];
    const float* g_bo   = (const float*)d_in[9];
    const float* be_bo  = (const float*)d_in[10];
    const float* W0_po  = (const float*)d_in[11];
    const float* b0_po  = (const float*)d_in[12];
    const float* g0_po  = (const float*)d_in[13];
    const float* be0_po = (const float*)d_in[14];
    const float* W_po   = (const float*)d_in[15];
    const float* b_po   = (const float*)d_in[16];
    const float* g_po   = (const float*)d_in[17];
    const float* be_po  = (const float*)d_in[18];
    float* out = (float*)d_out;

    static bool inited = false;
    static cudaStream_t s1, s2;
    static cudaEvent_t evRoot, ev1, ev2;
    if (!inited) {
        cudaStreamCreateWithFlags(&s1, cudaStreamNonBlocking);
        cudaStreamCreateWithFlags(&s2, cudaStreamNonBlocking);
        cudaEventCreateWithFlags(&evRoot, cudaEventDisableTiming);
        cudaEventCreateWithFlags(&ev1,    cudaEventDisableTiming);
        cudaEventCreateWithFlags(&ev2,    cudaEventDisableTiming);
        cudaFuncSetAttribute(gemm0_kernel,
                             cudaFuncAttributeMaxDynamicSharedMemorySize, GEMM_SMEM);
        cudaFuncSetAttribute(gemm_mma_kernel,
                             cudaFuncAttributeMaxDynamicSharedMemorySize, GEMM_SMEM);
        cudaFuncSetAttribute(mix_mma_kernel,
                             cudaFuncAttributeMaxDynamicSharedMemorySize, MIX_SMEM);
        inited = true;
    }

    __nv_bfloat16 *Ah96, *Al96;
    cudaGetSymbolAddress((void**)&Ah96, g_Ah96);
    cudaGetSymbolAddress((void**)&Al96, g_Al96);
    StackPtrs p0 = get_ptrs(0);
    StackPtrs p1 = get_ptrs(1);

    // shared adjacency split on the main (capture) stream
    asplit_kernel<<<36, 256>>>(A, Ah96, Al96);

    // fork
    cudaEventRecord(evRoot, 0);
    cudaStreamWaitEvent(s1, evRoot, 0);
    cudaStreamWaitEvent(s2, evRoot, 0);

    run_stack(s1, x_bo, 35, W0_bo, b0_bo, g0_bo, be0_bo, W_bo, b_bo, g_bo, be_bo,
              p0, Ah96, Al96, out);
    run_stack(s2, x_po, 40, W0_po, b0_po, g0_po, be0_po, W_po, b_po, g_po, be_po,
              p1, Ah96, Al96, out + EMB);

    // join
    cudaEventRecord(ev1, s1);
    cudaEventRecord(ev2, s2);
    cudaStreamWaitEvent(0, ev1, 0);
    cudaStreamWaitEvent(0, ev2, 0);
}